// round 14
// baseline (speedup 1.0000x reference)
#include <cuda_runtime.h>
#include <cstdint>

// PEPS 6x6, D=3, B=16 — quadrant decomposition, cluster of 4 CTAs per config.
// rank 0=TL, 1=TR, 2=BL, 3=BR (mirrored -> identical code per quadrant).
// WARP-LOCAL digit layout: group g = (c0*3+c1)*27 + w0*9 + w1*3 + w2, where
// w0,w1,w2 = column bonds (strides 9,3,1) and c0,c1 = cut bonds (81,27).
// 288 threads = 9 warps; warp (c0,c1) owns its 27-group block (lanes 0-26).
// Steps: A (fused sites 0-3), S4, B (fused 5+6), S7, S8. Only B crosses
// blocks (reads (c0,0)) -> ONE __syncthreads in the chain; others __syncwarp.
// Merge (R6-proven): rank0/2 pull peer S0 after cluster bar,
// M[v1,v2] = sum_{jg,lane} L[jg*27+v1]·R[jg*27+v2]; rank2 pushes M2; rank0 dots.

#define NTH 288
#define ATF 108

__device__ __forceinline__ float dot3(float4 a, float4 b) {
    return a.x * b.x + a.y * b.y + a.z * b.z;
}

__device__ __forceinline__ uint32_t smem_u32(const void* p) {
    uint32_t a;
    asm("{ .reg .u64 t; cvta.to.shared.u64 t, %1; cvt.u32.u64 %0, t; }"
        : "=r"(a) : "l"(p));
    return a;
}

__device__ __forceinline__ float ld_cluster_f32(uint32_t laddr, uint32_t rank) {
    uint32_t r; float v;
    asm volatile("mapa.shared::cluster.u32 %0, %1, %2;" : "=r"(r) : "r"(laddr), "r"(rank));
    asm volatile("ld.shared::cluster.f32 %0, [%1];" : "=f"(v) : "r"(r) : "memory");
    return v;
}

__device__ __forceinline__ void st_cluster_f32(uint32_t laddr, uint32_t rank, float v) {
    uint32_t r;
    asm volatile("mapa.shared::cluster.u32 %0, %1, %2;" : "=r"(r) : "r"(laddr), "r"(rank));
    asm volatile("st.shared::cluster.f32 [%0], %1;" :: "r"(r), "f"(v) : "memory");
}

#define CLUSTER_BAR() do { \
    asm volatile("barrier.cluster.arrive.aligned;" ::: "memory"); \
    asm volatile("barrier.cluster.wait.aligned;"   ::: "memory"); \
} while (0)

__global__ __launch_bounds__(NTH, 1) __cluster_dims__(4, 1, 1)
void peps_quad_kernel(const int* __restrict__ xcfg,
                      const float* __restrict__ T,
                      float* __restrict__ out) {
    __shared__ float4 S0[243];
    __shared__ float4 S1[243];
    __shared__ float  At[9 * ATF];
    __shared__ float  M[729];
    __shared__ float  M2[729];
    __shared__ int    sOff[36];
    __shared__ float  red[9];

    const int t = threadIdx.x;
    const int b = blockIdx.x >> 2;
    uint32_t rank;
    asm("mov.u32 %0, %%cluster_ctarank;" : "=r"(rank));
    const int bottom = (int)(rank >> 1);
    const int right  = (int)(rank & 1);

    const int warp = t >> 5, lane = t & 31;
    const int act  = (lane < 27);
    const int c0 = warp / 3, c1 = warp - 3 * c0;
    const int w0 = lane / 9, w1 = (lane / 3) % 3, w2 = lane % 3;
    const int g  = warp * 27 + lane;     // group index (valid when act)

    // sOff straight from gmem
    if (t < 36) {
        const int* xb = xcfg + b * 36;
        int xx = t / 6, yy = t % 6;
        int p  = xb[t];
        int pu = (xx > 0) ? xb[t - 6] : 0;
        int pd = (xx < 5) ? xb[t + 6] : 0;
        int pl = (yy > 0) ? xb[t - 1] : 0;
        int pr = (yy < 5) ? xb[t + 1] : 0;
        sOff[t] = (((p * 2 + pu) * 2 + pd) * 2 + pl) * 2 + pr;
    }
    __syncthreads();

    // Gather my quadrant's 9 site tensors: At[s][o][hp][a][ln].
    for (int i = t; i < 9 * ATF; i += NTH) {
        int s = i / ATF, r = i - s * ATF;
        int o  = r / 36;  r -= o * 36;
        int hp = r / 12;  r -= hp * 12;
        int a  = r >> 2,  ln = r & 3;
        float v = 0.0f;
        if (ln < 3) {
            int x = bottom ? 5 - s / 3 : s / 3;
            int y = right  ? 5 - s % 3 : s % 3;
            int u  = bottom ? o : a;
            int d  = bottom ? a : o;
            int l  = right ? hp : ln;
            int rr = right ? ln : hp;
            int site = x * 6 + y;
            v = T[site * 2592 + (((u * 3 + d) * 3 + l) * 3 + rr) * 32 + sOff[site]];
        }
        At[i] = v;
    }
    __syncthreads();

    const float4* Atv = (const float4*)At;

    // Step A: fused sites 0-3 -> own block. Nonzero only for c1==0 blocks:
    //   g_h1 = sum_h2 A1[w1,h2,h1]*A2[w2,c0,h2];  v_a = sum_h1 A0[a,h1]*g_h1
    //   out.h = sum_a v_a * A3[w0][h][a][0]
    if (act) {
        float4 vout = make_float4(0.0f, 0.0f, 0.0f, 0.0f);
        if (c1 == 0) {
            const float* A1 = At + ATF + w1 * 36;
            const float* A2 = At + 2 * ATF + w2 * 36 + c0 * 12;
            float g0 = A1[0] * A2[0] + A1[12] * A2[1] + A1[24] * A2[2];
            float g1 = A1[1] * A2[0] + A1[13] * A2[1] + A1[25] * A2[2];
            float g2 = A1[2] * A2[0] + A1[14] * A2[1] + A1[26] * A2[2];
            float v0 = At[0]  * g0 + At[12] * g1 + At[24] * g2;
            float v1 = At[36] * g0 + At[48] * g1 + At[60] * g2;
            float v2 = At[72] * g0 + At[84] * g1 + At[96] * g2;
            const float* A3 = At + 3 * ATF + w0 * 36;
            vout.x = v0 * A3[0]  + v1 * A3[4]  + v2 * A3[8];
            vout.y = v0 * A3[12] + v1 * A3[16] + v2 * A3[20];
            vout.z = v0 * A3[24] + v1 * A3[28] + v2 * A3[32];
        }
        S0[g] = vout;
    }
    __syncwarp();

    // S4: site 4, contracts w1 (stride 3), warp-local.
    if (act) {
        int base = g - w1 * 3;
        float4 x0 = S0[base], x1 = S0[base + 3], x2 = S0[base + 6];
        const float4* Av = Atv + 4 * 27 + w1 * 9;
        S1[g] = make_float4(
            dot3(x0, Av[0]) + dot3(x1, Av[1]) + dot3(x2, Av[2]),
            dot3(x0, Av[3]) + dot3(x1, Av[4]) + dot3(x2, Av[5]),
            dot3(x0, Av[6]) + dot3(x1, Av[7]) + dot3(x2, Av[8]), 0.0f);
    }
    __syncthreads();   // B reads block (c0,0) across warps

    // Step B: fused sites 5+6. Reads X = S1 block (c0,0):
    //   s[u6] = sum_u5 dot3( X[c0*81 + u6*9 + w1*3 + u5], A5[w2][c1][u5] )
    //   out.hp = sum_u6 s[u6] * A6[w0][hp][u6][0]
    if (act) {
        const float4* A5v = Atv + 5 * 27 + w2 * 9 + c1 * 3;
        float4 a50 = A5v[0], a51 = A5v[1], a52 = A5v[2];
        int xb = c0 * 81 + w1 * 3;
        float s0 = dot3(S1[xb],      a50) + dot3(S1[xb + 1],  a51) + dot3(S1[xb + 2],  a52);
        float s1 = dot3(S1[xb + 9],  a50) + dot3(S1[xb + 10], a51) + dot3(S1[xb + 11], a52);
        float s2 = dot3(S1[xb + 18], a50) + dot3(S1[xb + 19], a51) + dot3(S1[xb + 20], a52);
        const float* A6 = At + 6 * ATF + w0 * 36;
        S0[g] = make_float4(
            s0 * A6[0]  + s1 * A6[4]  + s2 * A6[8],
            s0 * A6[12] + s1 * A6[16] + s2 * A6[20],
            s0 * A6[24] + s1 * A6[28] + s2 * A6[32], 0.0f);
    }
    __syncwarp();

    // S7: site 7, contracts w1 (stride 3), warp-local.
    if (act) {
        int base = g - w1 * 3;
        float4 x0 = S0[base], x1 = S0[base + 3], x2 = S0[base + 6];
        const float4* Av = Atv + 7 * 27 + w1 * 9;
        S1[g] = make_float4(
            dot3(x0, Av[0]) + dot3(x1, Av[1]) + dot3(x2, Av[2]),
            dot3(x0, Av[3]) + dot3(x1, Av[4]) + dot3(x2, Av[5]),
            dot3(x0, Av[6]) + dot3(x1, Av[7]) + dot3(x2, Av[8]), 0.0f);
    }
    __syncwarp();

    // S8: site 8, contracts w2 (stride 1), warp-local. Final state in S0.
    if (act) {
        int base = g - w2;
        float4 x0 = S1[base], x1 = S1[base + 1], x2 = S1[base + 2];
        const float4* Av = Atv + 8 * 27 + w2 * 9;
        S0[g] = make_float4(
            dot3(x0, Av[0]) + dot3(x1, Av[1]) + dot3(x2, Av[2]),
            dot3(x0, Av[3]) + dot3(x1, Av[4]) + dot3(x2, Av[5]),
            dot3(x0, Av[6]) + dot3(x1, Av[7]) + dot3(x2, Av[8]), 0.0f);
    }

    CLUSTER_BAR();

    // Ranks 0 (top) and 2 (bottom): pull peer quadrant (rank+1) and merge.
    // M[v1,v2] = sum_{jg<9} dot3( S0[jg*27+v1], S1[jg*27+v2] )
    if (right == 0) {
        float* S1f = (float*)S1;
        uint32_t s0a = smem_u32(S0);
        for (int i = t; i < 972; i += NTH)
            S1f[i] = ld_cluster_f32(s0a + (uint32_t)i * 4u, rank + 1);
        __syncthreads();
        uint32_t m2a = smem_u32(M2);
        for (int v = t; v < 729; v += NTH) {
            int v1 = v / 27, v2 = v - 27 * (v / 27);
            float s = 0.0f;
            #pragma unroll
            for (int jg = 0; jg < 9; ++jg)
                s += dot3(S0[jg * 27 + v1], S1[jg * 27 + v2]);
            if (bottom) st_cluster_f32(m2a + (uint32_t)v * 4u, 0, s);
            else        M[v] = s;
        }
    }
    CLUSTER_BAR();

    if (rank == 0) {
        float s = 0.0f;
        for (int v = t; v < 729; v += NTH) s += M[v] * M2[v];
        #pragma unroll
        for (int o = 16; o; o >>= 1) s += __shfl_xor_sync(0xFFFFFFFFu, s, o);
        if (lane == 0) red[warp] = s;
        __syncthreads();
        if (t == 0) {
            float tt = 0.0f;
            #pragma unroll
            for (int w = 0; w < 9; ++w) tt += red[w];
            out[b] = tt;
        }
    }
}

extern "C" void kernel_launch(void* const* d_in, const int* in_sizes, int n_in,
                              void* d_out, int out_size) {
    const int*   xcfg = nullptr;
    const float* T    = nullptr;
    for (int i = 0; i < n_in; ++i) {
        if (in_sizes[i] == 576) xcfg = (const int*)d_in[i];
        else                    T    = (const float*)d_in[i];
    }
    float* out = (float*)d_out;
    peps_quad_kernel<<<64, NTH>>>(xcfg, T, out);
}